// round 16
// baseline (speedup 1.0000x reference)
#include <cuda_runtime.h>
#include <math.h>

#define SEQ 2048
#define DM  1024
#define NH  16
#define HD  64
#define LAT 256
#define NCTA 148

// Scratch — device globals (no allocation allowed). All half2-packed.
__device__ unsigned g_xh[SEQ * (DM / 2)];        // X, col pairs
__device__ unsigned g_wqh[(DM / 2) * DM];        // Wq, k-pair-major
__device__ unsigned g_wdkvh[(DM / 2) * LAT];     // Wdkv
__device__ unsigned g_wukh[(LAT / 2) * DM];      // Wuk
__device__ unsigned g_wuvh[(LAT / 2) * DM];      // Wuv
__device__ unsigned g_woh[(DM / 2) * DM];        // Wo
__device__ unsigned g_wwh[4 * (DM / 2) * 256];   // wheel_W
__device__ unsigned g_qh[SEQ * (DM / 2)];        // q, col pairs, pre-scaled
__device__ unsigned g_ckvh[SEQ * (LAT / 2)];     // c_kv, col pairs
__device__ unsigned g_kh[SEQ * (DM / 2)];        // k, col pairs
__device__ unsigned g_vt[(SEQ / 2) * DM];        // V pair-major rows
__device__ unsigned g_ctxh[SEQ * (DM / 2)];      // ctx, col pairs
__device__ unsigned g_bodyh[SEQ * (DM / 2)];     // body, col pairs

// Global software barrier state (zero-initialized).
__device__ unsigned g_cnt;
__device__ volatile unsigned g_phase;

// --------------------------------------------------------------------------
// helpers
// --------------------------------------------------------------------------
__device__ __forceinline__ float fex2(float x) {
    float y;
    asm("ex2.approx.f32 %0, %1;" : "=f"(y) : "f"(x));
    return y;
}
__device__ __forceinline__ unsigned packh2(float lo, float hi) {
    unsigned r;
    asm("cvt.rn.f16x2.f32 %0, %1, %2;" : "=r"(r) : "f"(hi), "f"(lo));
    return r;
}
__device__ __forceinline__ void mma_f16(float* c, const unsigned* a,
                                        unsigned b0, unsigned b1) {
    asm volatile(
        "mma.sync.aligned.m16n8k16.row.col.f32.f16.f16.f32 "
        "{%0,%1,%2,%3}, {%4,%5,%6,%7}, {%8,%9}, {%0,%1,%2,%3};"
        : "+f"(c[0]), "+f"(c[1]), "+f"(c[2]), "+f"(c[3])
        : "r"(a[0]), "r"(a[1]), "r"(a[2]), "r"(a[3]),
          "r"(b0), "r"(b1));
}
__device__ __forceinline__ void bar_g(int id) {
    asm volatile("bar.sync %0, %1;" :: "r"(id), "r"(128) : "memory");
}

// Grid-wide barrier: all 148 CTAs resident.
__device__ __forceinline__ void grid_bar(unsigned target) {
    __syncthreads();
    if (threadIdx.x == 0) {
        __threadfence();
        unsigned arr = atomicAdd(&g_cnt, 1u);
        if (arr == NCTA - 1) {
            atomicExch(&g_cnt, 0u);
            __threadfence();
            g_phase = target;
        } else {
            while (g_phase != target) { asm volatile("nanosleep.u32 64;"); }
            __threadfence();
        }
    }
    __syncthreads();
}

// --------------------------------------------------------------------------
// Phase 0: one-time fp32 -> packed-half2 conversion of inputs/weights.
// --------------------------------------------------------------------------
__device__ void conv_b(const float* __restrict__ W, unsigned* __restrict__ Wh,
                       int kp_cnt, int n4_shift, int gt, int NT)
{
    const int items = kp_cnt << n4_shift;
    const int N = 4 << n4_shift;
    for (int it = gt; it < items; it += NT) {
        int kp = it >> n4_shift;
        int n = (it & ((1 << n4_shift) - 1)) * 4;
        float4 a = *reinterpret_cast<const float4*>(&W[(long)(2 * kp) * N + n]);
        float4 b = *reinterpret_cast<const float4*>(&W[(long)(2 * kp + 1) * N + n]);
        uint4 u;
        u.x = packh2(a.x, b.x);
        u.y = packh2(a.y, b.y);
        u.z = packh2(a.z, b.z);
        u.w = packh2(a.w, b.w);
        *reinterpret_cast<uint4*>(&Wh[(long)kp * N + n]) = u;
    }
}

__device__ void conv_all(const float* X, const float* Wq, const float* Wdkv,
                         const float* Wuk, const float* Wuv, const float* Wo,
                         const float* wW)
{
    const int gt = blockIdx.x * 256 + threadIdx.x;
    const int NT = NCTA * 256;
    // X -> col pairs
    for (int it = gt; it < SEQ * (DM / 4); it += NT) {
        int row = it >> 8, t = it & 255;
        float4 x4 = *reinterpret_cast<const float4*>(&X[(long)row * DM + t * 4]);
        uint2 u = make_uint2(packh2(x4.x, x4.y), packh2(x4.z, x4.w));
        *reinterpret_cast<uint2*>(&g_xh[(long)row * (DM / 2) + 2 * t]) = u;
    }
    conv_b(Wq,   g_wqh,   DM / 2,  8, gt, NT);
    conv_b(Wdkv, g_wdkvh, DM / 2,  6, gt, NT);
    conv_b(Wuk,  g_wukh,  LAT / 2, 8, gt, NT);
    conv_b(Wuv,  g_wuvh,  LAT / 2, 8, gt, NT);
    conv_b(Wo,   g_woh,   DM / 2,  8, gt, NT);
    #pragma unroll
    for (int w = 0; w < 4; w++)
        conv_b(wW + (long)w * DM * 256, g_wwh + (long)w * (DM / 2) * 256,
               DM / 2, 6, gt, NT);
}

// --------------------------------------------------------------------------
// GEMM tile, fp16 m16n8k16, ALL-HALF staging (pure bit copies).
// A: packed col-pair source [row][ldah pairs]. B: k-pair-major [kp][ldbh].
// As segments: As[m*36 + (p&3)*8 + (p>>2)]. Bs: Bs[kp*132 + n].
// MODE 0: fp32 out (+bias). MODE 2: half2 col pairs (*oscale) -> Ch.
// MODE 3: half2 pair-major rows (V) -> Ch. MODE 4: fp32 out + half2 -> Ch.
// --------------------------------------------------------------------------
#define AP2 36
#define BP2 132
template <int MODE>
__device__ void gemm_tile(unsigned* smem,
    const unsigned* __restrict__ Ah, const unsigned* __restrict__ Bh,
    const float* __restrict__ bias, float* __restrict__ C,
    unsigned* __restrict__ Ch,
    int K, int ldah, int ldbh, int ldc, int m0, int n0, float oscale)
{
    unsigned* As = smem;                 // 128*36
    unsigned* Bs = smem + 128 * AP2;     // 16*132

    const int tid  = threadIdx.x;
    const int lane = tid & 31;
    const int warp = tid >> 5;
    const int g = lane >> 2;
    const int r = lane & 3;
    const int wm = warp & 3;
    const int wn = warp >> 2;

    float acc[2][8][4];
    #pragma unroll
    for (int i = 0; i < 2; i++)
        #pragma unroll
        for (int j = 0; j < 8; j++)
            #pragma unroll
            for (int t = 0; t < 4; t++) acc[i][j][t] = 0.f;

    for (int k0 = 0; k0 < K; k0 += 32) {
        const int kp0 = k0 >> 1;
        // A tile: 128 rows x 4 uint4 (16 pairs) — bit copy into segments
        #pragma unroll
        for (int e = 0; e < 2; e++) {
            int idx = e * 256 + tid;
            int m = idx >> 2, t = idx & 3;
            uint4 a4 = *reinterpret_cast<const uint4*>(
                &Ah[(long)(m0 + m) * ldah + kp0 + 4 * t]);
            unsigned* p = &As[m * AP2 + t];
            p[0]  = a4.x;
            p[8]  = a4.y;
            p[16] = a4.z;
            p[24] = a4.w;
        }
        // B tile: 16 kp x 128 — straight uint4 copy
        #pragma unroll
        for (int e = 0; e < 2; e++) {
            int idx = e * 256 + tid;
            int kp = idx >> 5, n = (idx & 31) * 4;
            *reinterpret_cast<uint4*>(&Bs[kp * BP2 + n]) =
                *reinterpret_cast<const uint4*>(&Bh[(long)(kp0 + kp) * ldbh + n0 + n]);
        }
        __syncthreads();

        uint4 AL[2], AH[2];
        #pragma unroll
        for (int i = 0; i < 2; i++) {
            int row = wm * 32 + i * 16;
            AL[i] = *reinterpret_cast<const uint4*>(&As[(row + g)     * AP2 + r * 8]);
            AH[i] = *reinterpret_cast<const uint4*>(&As[(row + g + 8) * AP2 + r * 8]);
        }
        #pragma unroll
        for (int kt = 0; kt < 2; kt++) {
            unsigned a[2][4];
            a[0][0] = kt ? AL[0].z : AL[0].x;
            a[0][1] = kt ? AH[0].z : AH[0].x;
            a[0][2] = kt ? AL[0].w : AL[0].y;
            a[0][3] = kt ? AH[0].w : AH[0].y;
            a[1][0] = kt ? AL[1].z : AL[1].x;
            a[1][1] = kt ? AH[1].z : AH[1].x;
            a[1][2] = kt ? AL[1].w : AL[1].y;
            a[1][3] = kt ? AH[1].w : AH[1].y;
            #pragma unroll
            for (int j = 0; j < 8; j++) {
                int col = wn * 64 + j * 8;
                unsigned b0 = Bs[(kt * 8 + r)     * BP2 + col + g];
                unsigned b1 = Bs[(kt * 8 + r + 4) * BP2 + col + g];
                mma_f16(acc[0][j], a[0], b0, b1);
                mma_f16(acc[1][j], a[1], b0, b1);
            }
        }
        __syncthreads();
    }

    #pragma unroll
    for (int i = 0; i < 2; i++) {
        int row = m0 + wm * 32 + i * 16;
        #pragma unroll
        for (int j = 0; j < 8; j++) {
            int col = n0 + wn * 64 + j * 8 + 2 * r;
            float c00 = acc[i][j][0], c01 = acc[i][j][1];
            float c10 = acc[i][j][2], c11 = acc[i][j][3];
            if (MODE == 3) {
                float d00 = __shfl_down_sync(0xffffffffu, c00, 4);
                float d01 = __shfl_down_sync(0xffffffffu, c01, 4);
                float d10 = __shfl_down_sync(0xffffffffu, c10, 4);
                float d11 = __shfl_down_sync(0xffffffffu, c11, 4);
                if (!(g & 1)) {
                    int kp  = (row + g) >> 1;
                    int kp2 = (row + g + 8) >> 1;
                    uint2 v0 = make_uint2(packh2(c00, d00), packh2(c01, d01));
                    uint2 v1 = make_uint2(packh2(c10, d10), packh2(c11, d11));
                    *reinterpret_cast<uint2*>(&Ch[(long)kp  * DM + col]) = v0;
                    *reinterpret_cast<uint2*>(&Ch[(long)kp2 * DM + col]) = v1;
                }
            } else if (MODE == 2) {
                int ldh = ldc >> 1;
                Ch[(long)(row + g)     * ldh + (col >> 1)] =
                    packh2(c00 * oscale, c01 * oscale);
                Ch[(long)(row + g + 8) * ldh + (col >> 1)] =
                    packh2(c10 * oscale, c11 * oscale);
            } else if (MODE == 4) {
                *reinterpret_cast<float2*>(&C[(long)(row + g) * ldc + col]) =
                    make_float2(c00, c01);
                *reinterpret_cast<float2*>(&C[(long)(row + g + 8) * ldc + col]) =
                    make_float2(c10, c11);
                Ch[(long)(row + g)     * (DM / 2) + (col >> 1)] = packh2(c00, c01);
                Ch[(long)(row + g + 8) * (DM / 2) + (col >> 1)] = packh2(c10, c11);
            } else {
                float b0 = 0.f, b1 = 0.f;
                if (bias) { b0 = bias[col]; b1 = bias[col + 1]; }
                *reinterpret_cast<float2*>(&C[(long)(row + g) * ldc + col]) =
                    make_float2(c00 + b0, c01 + b1);
                *reinterpret_cast<float2*>(&C[(long)(row + g + 8) * ldc + col]) =
                    make_float2(c10 + b0, c11 + b1);
            }
        }
    }
}

// --------------------------------------------------------------------------
// Flash group — full fp16 path (proven R15); epilogue now writes packed
// half2 col pairs to g_ctxh. Group smem: 3072 + 2304 + 4*1536 = 11520 w.
// --------------------------------------------------------------------------
__device__ void flash_group(unsigned* KB, int barid, int h, int i0)
{
    unsigned* VT = KB + 3072;
    unsigned* QB = KB + 5376;

    const int tid  = threadIdx.x & 127;
    const int lane = tid & 31;
    const int warp = tid >> 5;
    const int g = lane >> 2;
    const int r = lane & 3;
    const int wbase = warp * 1536;

    #pragma unroll
    for (int e = 0; e < 8; e++) {
        int idx = e * 128 + tid;
        int row = idx >> 3, t = idx & 7;
        uint4 q4 = *reinterpret_cast<const uint4*>(
            &g_qh[(long)(i0 + row) * (DM / 2) + h * 32 + t * 4]);
        unsigned* p = &QB[(row >> 5) * 1536 + (row & 31) * 48 + t];
        p[0]  = q4.x;
        p[12] = q4.y;
        p[24] = q4.z;
        p[36] = q4.w;
    }
    bar_g(barid);

    unsigned qa[2][4][4];
    #pragma unroll
    for (int i = 0; i < 2; i++) {
        const uint4* lo4 = reinterpret_cast<const uint4*>(
            &QB[wbase + (i * 16 + g) * 48 + r * 12]);
        const uint4* hi4 = reinterpret_cast<const uint4*>(
            &QB[wbase + (i * 16 + g + 8) * 48 + r * 12]);
        uint4 L[2] = {lo4[0], lo4[1]};
        uint4 H[2] = {hi4[0], hi4[1]};
        const unsigned* lo = reinterpret_cast<const unsigned*>(L);
        const unsigned* hi = reinterpret_cast<const unsigned*>(H);
        #pragma unroll
        for (int kt = 0; kt < 4; kt++) {
            qa[i][kt][0] = lo[2 * kt];
            qa[i][kt][1] = hi[2 * kt];
            qa[i][kt][2] = lo[2 * kt + 1];
            qa[i][kt][3] = hi[2 * kt + 1];
        }
    }

    float lsum[2][2];
    lsum[0][0] = lsum[0][1] = lsum[1][0] = lsum[1][1] = 0.f;
    float o[2][8][4];
    #pragma unroll
    for (int i = 0; i < 2; i++)
        #pragma unroll
        for (int j = 0; j < 8; j++)
            #pragma unroll
            for (int t = 0; t < 4; t++) o[i][j][t] = 0.f;

    for (int j0 = 0; j0 < SEQ; j0 += 64) {
        #pragma unroll
        for (int e = 0; e < 4; e++) {
            int idx = e * 128 + tid;
            int key = idx >> 3, t = idx & 7;
            uint4 k4 = *reinterpret_cast<const uint4*>(
                &g_kh[(long)(j0 + key) * (DM / 2) + h * 32 + t * 4]);
            unsigned* p = &KB[key * 48 + t];
            p[0]  = k4.x;
            p[12] = k4.y;
            p[24] = k4.z;
            p[36] = k4.w;
        }
        #pragma unroll
        for (int e = 0; e < 4; e++) {
            int idx = e * 128 + tid;
            int kp = idx >> 4, dq = idx & 15;
            uint4 v4 = *reinterpret_cast<const uint4*>(
                &g_vt[(long)((j0 >> 1) + kp) * DM + h * HD + dq * 4]);
            *reinterpret_cast<uint4*>(&VT[kp * 72 + dq * 4]) = v4;
        }
        bar_g(barid);

        #pragma unroll
        for (int half = 0; half < 2; half++) {
            const int nb = half * 4;

            float s[2][4][4];
            #pragma unroll
            for (int nt = 0; nt < 4; nt++) {
                #pragma unroll
                for (int i = 0; i < 2; i++)
                    #pragma unroll
                    for (int t = 0; t < 4; t++) s[i][nt][t] = 0.f;
                const uint4* kp4 = reinterpret_cast<const uint4*>(
                    &KB[((nb + nt) * 8 + g) * 48 + r * 12]);
                uint4 W0 = kp4[0], W1 = kp4[1];
                unsigned w[8] = {W0.x, W0.y, W0.z, W0.w, W1.x, W1.y, W1.z, W1.w};
                #pragma unroll
                for (int kt = 0; kt < 4; kt++) {
                    mma_f16(s[0][nt], qa[0][kt], w[2 * kt], w[2 * kt + 1]);
                    mma_f16(s[1][nt], qa[1][kt], w[2 * kt], w[2 * kt + 1]);
                }
            }

            #pragma unroll
            for (int i = 0; i < 2; i++)
                #pragma unroll
                for (int nt = 0; nt < 4; nt++) {
                    s[i][nt][0] = fex2(s[i][nt][0]);
                    s[i][nt][1] = fex2(s[i][nt][1]);
                    s[i][nt][2] = fex2(s[i][nt][2]);
                    s[i][nt][3] = fex2(s[i][nt][3]);
                    lsum[i][0] += s[i][nt][0] + s[i][nt][1];
                    lsum[i][1] += s[i][nt][2] + s[i][nt][3];
                }

            unsigned pa[2][2][4];
            #pragma unroll
            for (int i = 0; i < 2; i++)
                #pragma unroll
                for (int kt2 = 0; kt2 < 2; kt2++) {
                    pa[i][kt2][0] = packh2(s[i][2 * kt2][0],     s[i][2 * kt2][1]);
                    pa[i][kt2][1] = packh2(s[i][2 * kt2][2],     s[i][2 * kt2][3]);
                    pa[i][kt2][2] = packh2(s[i][2 * kt2 + 1][0], s[i][2 * kt2 + 1][1]);
                    pa[i][kt2][3] = packh2(s[i][2 * kt2 + 1][2], s[i][2 * kt2 + 1][3]);
                }

            #pragma unroll
            for (int kt2 = 0; kt2 < 2; kt2++) {
                const int kpb = half * 16 + kt2 * 8;
                #pragma unroll
                for (int nt = 0; nt < 8; nt++) {
                    unsigned b0 = VT[(kpb + r)     * 72 + nt * 8 + g];
                    unsigned b1 = VT[(kpb + r + 4) * 72 + nt * 8 + g];
                    mma_f16(o[0][nt], pa[0][kt2], b0, b1);
                    mma_f16(o[1][nt], pa[1][kt2], b0, b1);
                }
            }
        }
        bar_g(barid);
    }

    const int qb = warp * 32;
    #pragma unroll
    for (int i = 0; i < 2; i++) {
        float l0 = lsum[i][0], l1 = lsum[i][1];
        l0 += __shfl_xor_sync(0xffffffffu, l0, 1);
        l0 += __shfl_xor_sync(0xffffffffu, l0, 2);
        l1 += __shfl_xor_sync(0xffffffffu, l1, 1);
        l1 += __shfl_xor_sync(0xffffffffu, l1, 2);
        float inv0 = 1.0f / l0, inv1 = 1.0f / l1;
        #pragma unroll
        for (int nt = 0; nt < 8; nt++) {
            int pcol = h * 32 + nt * 4 + r;
            g_ctxh[(long)(i0 + qb + i * 16 + g) * (DM / 2) + pcol] =
                packh2(o[i][nt][0] * inv0, o[i][nt][1] * inv0);
            g_ctxh[(long)(i0 + qb + i * 16 + g + 8) * (DM / 2) + pcol] =
                packh2(o[i][nt][2] * inv1, o[i][nt][3] * inv1);
        }
    }
}

// --------------------------------------------------------------------------
// Persistent mega-kernel: 148 CTAs x 256 threads, software grid barriers.
// --------------------------------------------------------------------------
__global__ void __launch_bounds__(256, 1) mega(
    const float* __restrict__ X,  const float* __restrict__ Wq,
    const float* __restrict__ Wdkv, const float* __restrict__ Wuk,
    const float* __restrict__ Wuv, const float* __restrict__ Wo,
    const float* __restrict__ wW, const float* __restrict__ wb,
    float* __restrict__ out)
{
    extern __shared__ unsigned smem[];
    const unsigned ph0 = g_phase;
    const int c = blockIdx.x;
    const float QSCALE = 0.125f * 1.4426950408889634f;

    // Phase 0: fp32 -> half conversions (once per run)
    conv_all(X, Wq, Wdkv, Wuk, Wuv, Wo, wW);
    grid_bar(ph0 + 1);

    // Phase A: 32 ckv + 116 q
    if (c < 32) {
        gemm_tile<2>(smem, g_xh, g_wdkvh, nullptr, nullptr, g_ckvh,
                     DM, DM / 2, LAT, LAT, (c >> 1) * 128, (c & 1) * 128, 1.f);
    } else {
        int qi = c - 32;
        gemm_tile<2>(smem, g_xh, g_wqh, nullptr, nullptr, g_qh,
                     DM, DM / 2, DM, DM, (qi >> 3) * 128, (qi & 7) * 128, QSCALE);
    }
    grid_bar(ph0 + 2);

    // Phase B: 128 k + 128 v + 12 leftover q
    for (int t = c; t < 268; t += NCTA) {
        if (t < 128) {
            gemm_tile<2>(smem, g_ckvh, g_wukh, nullptr, nullptr, g_kh,
                         LAT, LAT / 2, DM, DM, (t >> 3) * 128, (t & 7) * 128, 1.f);
        } else if (t < 256) {
            int tt = t - 128;
            gemm_tile<3>(smem, g_ckvh, g_wuvh, nullptr, nullptr, g_vt,
                         LAT, LAT / 2, DM, DM, (tt >> 3) * 128, (tt & 7) * 128, 1.f);
        } else {
            int qi = 116 + (t - 256);
            gemm_tile<2>(smem, g_xh, g_wqh, nullptr, nullptr, g_qh,
                         DM, DM / 2, DM, DM, (qi >> 3) * 128, (qi & 7) * 128, QSCALE);
        }
    }
    grid_bar(ph0 + 3);

    // Phase C: flash — two 4-warp groups per CTA, 256 (head, qtile) tasks
    {
        int group = threadIdx.x >> 7;
        int t = c * 2 + group;
        if (t < 256)
            flash_group(smem + group * 11520, 1 + group, t >> 4, (t & 15) * 128);
    }
    grid_bar(ph0 + 4);

    // Phase D: body -> out[:, 0:1024] fp32 + g_bodyh half
    if (c < 128)
        gemm_tile<4>(smem, g_ctxh, g_woh, nullptr, out, g_bodyh,
                     DM, DM / 2, DM, 2048, (c >> 3) * 128, (c & 7) * 128, 1.f);
    grid_bar(ph0 + 5);

    // Phase E: wheels -> out[:, 1024:2048]
    if (c < 128) {
        int w = c >> 5, tt = c & 31;
        gemm_tile<0>(smem, g_bodyh, g_wwh + (long)w * (DM / 2) * 256,
                     wb + w * 256, out + 1024 + w * 256, nullptr,
                     DM, DM / 2, 256, 2048, (tt >> 1) * 128, (tt & 1) * 128, 1.f);
    }
}

// --------------------------------------------------------------------------
// Launcher: ONE kernel.
// --------------------------------------------------------------------------
extern "C" void kernel_launch(void* const* d_in, const int* in_sizes, int n_in,
                              void* d_out, int out_size)
{
    const float* X    = (const float*)d_in[0];
    const float* Wq   = (const float*)d_in[1];
    const float* Wdkv = (const float*)d_in[2];
    const float* Wuk  = (const float*)d_in[3];
    const float* Wuv  = (const float*)d_in[4];
    const float* Wo   = (const float*)d_in[5];
    const float* wW   = (const float*)d_in[6];
    const float* wb   = (const float*)d_in[7];
    float* out = (float*)d_out;

    const int smem = 23040 * (int)sizeof(unsigned);  // 92160 B
    cudaFuncSetAttribute(mega, cudaFuncAttributeMaxDynamicSharedMemorySize, smem);
    mega<<<NCTA, 256, smem>>>(X, Wq, Wdkv, Wuk, Wuv, Wo, wW, wb, out);
}

// round 17
// speedup vs baseline: 1.2026x; 1.2026x over previous
#include <cuda_runtime.h>
#include <math.h>

#define SEQ 2048
#define DM  1024
#define NH  16
#define HD  64
#define LAT 256
#define NCTA 148

// Scratch — device globals (no allocation allowed). All half2-packed.
__device__ unsigned g_xh[SEQ * (DM / 2)];        // X, col pairs
__device__ unsigned g_wqh[(DM / 2) * DM];        // Wq, k-pair-major
__device__ unsigned g_wdkvh[(DM / 2) * LAT];     // Wdkv
__device__ unsigned g_wukh[(LAT / 2) * DM];      // Wuk
__device__ unsigned g_wuvh[(LAT / 2) * DM];      // Wuv
__device__ unsigned g_woh[(DM / 2) * DM];        // Wo
__device__ unsigned g_wwh[4 * (DM / 2) * 256];   // wheel_W
__device__ unsigned g_qh[SEQ * (DM / 2)];        // q, col pairs, pre-scaled
__device__ unsigned g_ckvh[SEQ * (LAT / 2)];     // c_kv, col pairs
__device__ unsigned g_kh[SEQ * (DM / 2)];        // k, col pairs
__device__ unsigned g_vt[(SEQ / 2) * DM];        // V pair-major rows
__device__ unsigned g_ctxh[SEQ * (DM / 2)];      // ctx, col pairs
__device__ unsigned g_bodyh[SEQ * (DM / 2)];     // body, col pairs

// Global software barrier state (zero-initialized).
__device__ unsigned g_cnt;
__device__ volatile unsigned g_phase;

// --------------------------------------------------------------------------
// helpers
// --------------------------------------------------------------------------
__device__ __forceinline__ float fex2(float x) {
    float y;
    asm("ex2.approx.f32 %0, %1;" : "=f"(y) : "f"(x));
    return y;
}
__device__ __forceinline__ unsigned packh2(float lo, float hi) {
    unsigned r;
    asm("cvt.rn.f16x2.f32 %0, %1, %2;" : "=r"(r) : "f"(hi), "f"(lo));
    return r;
}
__device__ __forceinline__ void mma_f16(float* c, const unsigned* a,
                                        unsigned b0, unsigned b1) {
    asm volatile(
        "mma.sync.aligned.m16n8k16.row.col.f32.f16.f16.f32 "
        "{%0,%1,%2,%3}, {%4,%5,%6,%7}, {%8,%9}, {%0,%1,%2,%3};"
        : "+f"(c[0]), "+f"(c[1]), "+f"(c[2]), "+f"(c[3])
        : "r"(a[0]), "r"(a[1]), "r"(a[2]), "r"(a[3]),
          "r"(b0), "r"(b1));
}
__device__ __forceinline__ void bar_g(int id) {
    asm volatile("bar.sync %0, %1;" :: "r"(id), "r"(128) : "memory");
}

// Grid-wide barrier: all 148 CTAs resident.
__device__ __forceinline__ void grid_bar(unsigned target) {
    __syncthreads();
    if (threadIdx.x == 0) {
        __threadfence();
        unsigned arr = atomicAdd(&g_cnt, 1u);
        if (arr == NCTA - 1) {
            atomicExch(&g_cnt, 0u);
            __threadfence();
            g_phase = target;
        } else {
            while (g_phase != target) { asm volatile("nanosleep.u32 64;"); }
            __threadfence();
        }
    }
    __syncthreads();
}

// --------------------------------------------------------------------------
// Phase 0: one-time fp32 -> packed-half2 conversion of inputs/weights.
// --------------------------------------------------------------------------
__device__ void conv_b(const float* __restrict__ W, unsigned* __restrict__ Wh,
                       int kp_cnt, int n4_shift, int gt, int NT)
{
    const int items = kp_cnt << n4_shift;
    const int N = 4 << n4_shift;
    for (int it = gt; it < items; it += NT) {
        int kp = it >> n4_shift;
        int n = (it & ((1 << n4_shift) - 1)) * 4;
        float4 a = *reinterpret_cast<const float4*>(&W[(long)(2 * kp) * N + n]);
        float4 b = *reinterpret_cast<const float4*>(&W[(long)(2 * kp + 1) * N + n]);
        uint4 u;
        u.x = packh2(a.x, b.x);
        u.y = packh2(a.y, b.y);
        u.z = packh2(a.z, b.z);
        u.w = packh2(a.w, b.w);
        *reinterpret_cast<uint4*>(&Wh[(long)kp * N + n]) = u;
    }
}

__device__ void conv_all(const float* X, const float* Wq, const float* Wdkv,
                         const float* Wuk, const float* Wuv, const float* Wo,
                         const float* wW)
{
    const int gt = blockIdx.x * 256 + threadIdx.x;
    const int NT = NCTA * 256;
    for (int it = gt; it < SEQ * (DM / 4); it += NT) {
        int row = it >> 8, t = it & 255;
        float4 x4 = *reinterpret_cast<const float4*>(&X[(long)row * DM + t * 4]);
        uint2 u = make_uint2(packh2(x4.x, x4.y), packh2(x4.z, x4.w));
        *reinterpret_cast<uint2*>(&g_xh[(long)row * (DM / 2) + 2 * t]) = u;
    }
    conv_b(Wq,   g_wqh,   DM / 2,  8, gt, NT);
    conv_b(Wdkv, g_wdkvh, DM / 2,  6, gt, NT);
    conv_b(Wuk,  g_wukh,  LAT / 2, 8, gt, NT);
    conv_b(Wuv,  g_wuvh,  LAT / 2, 8, gt, NT);
    conv_b(Wo,   g_woh,   DM / 2,  8, gt, NT);
    #pragma unroll
    for (int w = 0; w < 4; w++)
        conv_b(wW + (long)w * DM * 256, g_wwh + (long)w * (DM / 2) * 256,
               DM / 2, 6, gt, NT);
}

// --------------------------------------------------------------------------
// GEMM tile, fp16 m16n8k16, all-half staging, SOFTWARE-PIPELINED K loop:
// smem ping-pong double buffer; LDGs for tile k+1 issue before the mma
// block on tile k (load latency hidden); ONE barrier per iteration.
// Buffer stride 6720 w (As 128*36 + Bs 16*132); two buffers = 13440 w.
// MODE 0: fp32 out (+bias). MODE 2: half2 col pairs (*oscale) -> Ch.
// MODE 3: half2 pair-major rows (V) -> Ch. MODE 4: fp32 + half2 -> Ch.
// --------------------------------------------------------------------------
#define AP2 36
#define BP2 132
#define GBUF 6720
template <int MODE>
__device__ void gemm_tile(unsigned* smem,
    const unsigned* __restrict__ Ah, const unsigned* __restrict__ Bh,
    const float* __restrict__ bias, float* __restrict__ C,
    unsigned* __restrict__ Ch,
    int K, int ldah, int ldbh, int ldc, int m0, int n0, float oscale)
{
    const int tid  = threadIdx.x;
    const int lane = tid & 31;
    const int warp = tid >> 5;
    const int g = lane >> 2;
    const int r = lane & 3;
    const int wm = warp & 3;
    const int wn = warp >> 2;

    // Per-thread staging coordinates (fixed).
    const int am0 = (tid >> 2), at0 = (tid & 3);           // e=0: A row/seg
    const int am1 = ((256 + tid) >> 2), at1 = at0;         // e=1
    const int bk0 = (tid >> 5), bn0 = (tid & 31) * 4;      // e=0: B kp/n
    const int bk1 = ((256 + tid) >> 5), bn1 = bn0;         // e=1

    float acc[2][8][4];
    #pragma unroll
    for (int i = 0; i < 2; i++)
        #pragma unroll
        for (int j = 0; j < 8; j++)
            #pragma unroll
            for (int t = 0; t < 4; t++) acc[i][j][t] = 0.f;

    // Prologue: load + store tile 0.
    uint4 ar0, ar1, br0, br1;
    ar0 = *reinterpret_cast<const uint4*>(&Ah[(long)(m0 + am0) * ldah + 4 * at0]);
    ar1 = *reinterpret_cast<const uint4*>(&Ah[(long)(m0 + am1) * ldah + 4 * at1]);
    br0 = *reinterpret_cast<const uint4*>(&Bh[(long)bk0 * ldbh + n0 + bn0]);
    br1 = *reinterpret_cast<const uint4*>(&Bh[(long)bk1 * ldbh + n0 + bn1]);
    {
        unsigned* As = smem;
        unsigned* Bs = smem + 128 * AP2;
        unsigned* p0 = &As[am0 * AP2 + at0];
        p0[0] = ar0.x; p0[8] = ar0.y; p0[16] = ar0.z; p0[24] = ar0.w;
        unsigned* p1 = &As[am1 * AP2 + at1];
        p1[0] = ar1.x; p1[8] = ar1.y; p1[16] = ar1.z; p1[24] = ar1.w;
        *reinterpret_cast<uint4*>(&Bs[bk0 * BP2 + bn0]) = br0;
        *reinterpret_cast<uint4*>(&Bs[bk1 * BP2 + bn1]) = br1;
    }
    __syncthreads();

    int cur = 0;
    for (int k0 = 0; k0 < K; k0 += 32) {
        const bool more = (k0 + 32) < K;
        // Issue next tile's LDGs now; consumed after the mma block.
        if (more) {
            const int kp = (k0 + 32) >> 1;
            ar0 = *reinterpret_cast<const uint4*>(
                &Ah[(long)(m0 + am0) * ldah + kp + 4 * at0]);
            ar1 = *reinterpret_cast<const uint4*>(
                &Ah[(long)(m0 + am1) * ldah + kp + 4 * at1]);
            br0 = *reinterpret_cast<const uint4*>(
                &Bh[(long)(kp + bk0) * ldbh + n0 + bn0]);
            br1 = *reinterpret_cast<const uint4*>(
                &Bh[(long)(kp + bk1) * ldbh + n0 + bn1]);
        }

        unsigned* As = smem + cur * GBUF;
        unsigned* Bs = smem + cur * GBUF + 128 * AP2;

        uint4 AL[2], AH[2];
        #pragma unroll
        for (int i = 0; i < 2; i++) {
            int row = wm * 32 + i * 16;
            AL[i] = *reinterpret_cast<const uint4*>(&As[(row + g)     * AP2 + r * 8]);
            AH[i] = *reinterpret_cast<const uint4*>(&As[(row + g + 8) * AP2 + r * 8]);
        }
        #pragma unroll
        for (int kt = 0; kt < 2; kt++) {
            unsigned a[2][4];
            a[0][0] = kt ? AL[0].z : AL[0].x;
            a[0][1] = kt ? AH[0].z : AH[0].x;
            a[0][2] = kt ? AL[0].w : AL[0].y;
            a[0][3] = kt ? AH[0].w : AH[0].y;
            a[1][0] = kt ? AL[1].z : AL[1].x;
            a[1][1] = kt ? AH[1].z : AH[1].x;
            a[1][2] = kt ? AL[1].w : AL[1].y;
            a[1][3] = kt ? AH[1].w : AH[1].y;
            #pragma unroll
            for (int j = 0; j < 8; j++) {
                int col = wn * 64 + j * 8;
                unsigned b0 = Bs[(kt * 8 + r)     * BP2 + col + g];
                unsigned b1 = Bs[(kt * 8 + r + 4) * BP2 + col + g];
                mma_f16(acc[0][j], a[0], b0, b1);
                mma_f16(acc[1][j], a[1], b0, b1);
            }
        }

        if (more) {
            unsigned* Asn = smem + (cur ^ 1) * GBUF;
            unsigned* Bsn = smem + (cur ^ 1) * GBUF + 128 * AP2;
            unsigned* p0 = &Asn[am0 * AP2 + at0];
            p0[0] = ar0.x; p0[8] = ar0.y; p0[16] = ar0.z; p0[24] = ar0.w;
            unsigned* p1 = &Asn[am1 * AP2 + at1];
            p1[0] = ar1.x; p1[8] = ar1.y; p1[16] = ar1.z; p1[24] = ar1.w;
            *reinterpret_cast<uint4*>(&Bsn[bk0 * BP2 + bn0]) = br0;
            *reinterpret_cast<uint4*>(&Bsn[bk1 * BP2 + bn1]) = br1;
        }
        __syncthreads();
        cur ^= 1;
    }

    #pragma unroll
    for (int i = 0; i < 2; i++) {
        int row = m0 + wm * 32 + i * 16;
        #pragma unroll
        for (int j = 0; j < 8; j++) {
            int col = n0 + wn * 64 + j * 8 + 2 * r;
            float c00 = acc[i][j][0], c01 = acc[i][j][1];
            float c10 = acc[i][j][2], c11 = acc[i][j][3];
            if (MODE == 3) {
                float d00 = __shfl_down_sync(0xffffffffu, c00, 4);
                float d01 = __shfl_down_sync(0xffffffffu, c01, 4);
                float d10 = __shfl_down_sync(0xffffffffu, c10, 4);
                float d11 = __shfl_down_sync(0xffffffffu, c11, 4);
                if (!(g & 1)) {
                    int kp  = (row + g) >> 1;
                    int kp2 = (row + g + 8) >> 1;
                    uint2 v0 = make_uint2(packh2(c00, d00), packh2(c01, d01));
                    uint2 v1 = make_uint2(packh2(c10, d10), packh2(c11, d11));
                    *reinterpret_cast<uint2*>(&Ch[(long)kp  * DM + col]) = v0;
                    *reinterpret_cast<uint2*>(&Ch[(long)kp2 * DM + col]) = v1;
                }
            } else if (MODE == 2) {
                int ldh = ldc >> 1;
                Ch[(long)(row + g)     * ldh + (col >> 1)] =
                    packh2(c00 * oscale, c01 * oscale);
                Ch[(long)(row + g + 8) * ldh + (col >> 1)] =
                    packh2(c10 * oscale, c11 * oscale);
            } else if (MODE == 4) {
                *reinterpret_cast<float2*>(&C[(long)(row + g) * ldc + col]) =
                    make_float2(c00, c01);
                *reinterpret_cast<float2*>(&C[(long)(row + g + 8) * ldc + col]) =
                    make_float2(c10, c11);
                Ch[(long)(row + g)     * (DM / 2) + (col >> 1)] = packh2(c00, c01);
                Ch[(long)(row + g + 8) * (DM / 2) + (col >> 1)] = packh2(c10, c11);
            } else {
                float b0 = 0.f, b1 = 0.f;
                if (bias) { b0 = bias[col]; b1 = bias[col + 1]; }
                *reinterpret_cast<float2*>(&C[(long)(row + g) * ldc + col]) =
                    make_float2(c00 + b0, c01 + b1);
                *reinterpret_cast<float2*>(&C[(long)(row + g + 8) * ldc + col]) =
                    make_float2(c10 + b0, c11 + b1);
            }
        }
    }
}

// --------------------------------------------------------------------------
// Flash group — full fp16 path (proven R15/R16). Epilogue writes packed
// half2 col pairs to g_ctxh. Group smem: 3072 + 2304 + 4*1536 = 11520 w.
// --------------------------------------------------------------------------
__device__ void flash_group(unsigned* KB, int barid, int h, int i0)
{
    unsigned* VT = KB + 3072;
    unsigned* QB = KB + 5376;

    const int tid  = threadIdx.x & 127;
    const int lane = tid & 31;
    const int warp = tid >> 5;
    const int g = lane >> 2;
    const int r = lane & 3;
    const int wbase = warp * 1536;

    #pragma unroll
    for (int e = 0; e < 8; e++) {
        int idx = e * 128 + tid;
        int row = idx >> 3, t = idx & 7;
        uint4 q4 = *reinterpret_cast<const uint4*>(
            &g_qh[(long)(i0 + row) * (DM / 2) + h * 32 + t * 4]);
        unsigned* p = &QB[(row >> 5) * 1536 + (row & 31) * 48 + t];
        p[0]  = q4.x;
        p[12] = q4.y;
        p[24] = q4.z;
        p[36] = q4.w;
    }
    bar_g(barid);

    unsigned qa[2][4][4];
    #pragma unroll
    for (int i = 0; i < 2; i++) {
        const uint4* lo4 = reinterpret_cast<const uint4*>(
            &QB[wbase + (i * 16 + g) * 48 + r * 12]);
        const uint4* hi4 = reinterpret_cast<const uint4*>(
            &QB[wbase + (i * 16 + g + 8) * 48 + r * 12]);
        uint4 L[2] = {lo4[0], lo4[1]};
        uint4 H[2] = {hi4[0], hi4[1]};
        const unsigned* lo = reinterpret_cast<const unsigned*>(L);
        const unsigned* hi = reinterpret_cast<const unsigned*>(H);
        #pragma unroll
        for (int kt = 0; kt < 4; kt++) {
            qa[i][kt][0] = lo[2 * kt];
            qa[i][kt][1] = hi[2 * kt];
            qa[i][kt][2] = lo[2 * kt + 1];
            qa[i][kt][3] = hi[2 * kt + 1];
        }
    }

    float lsum[2][2];
    lsum[0][0] = lsum[0][1] = lsum[1][0] = lsum[1][1] = 0.f;
    float o[2][8][4];
    #pragma unroll
    for (int i = 0; i < 2; i++)
        #pragma unroll
        for (int j = 0; j < 8; j++)
            #pragma unroll
            for (int t = 0; t < 4; t++) o[i][j][t] = 0.f;

    for (int j0 = 0; j0 < SEQ; j0 += 64) {
        #pragma unroll
        for (int e = 0; e < 4; e++) {
            int idx = e * 128 + tid;
            int key = idx >> 3, t = idx & 7;
            uint4 k4 = *reinterpret_cast<const uint4*>(
                &g_kh[(long)(j0 + key) * (DM / 2) + h * 32 + t * 4]);
            unsigned* p = &KB[key * 48 + t];
            p[0]  = k4.x;
            p[12] = k4.y;
            p[24] = k4.z;
            p[36] = k4.w;
        }
        #pragma unroll
        for (int e = 0; e < 4; e++) {
            int idx = e * 128 + tid;
            int kp = idx >> 4, dq = idx & 15;
            uint4 v4 = *reinterpret_cast<const uint4*>(
                &g_vt[(long)((j0 >> 1) + kp) * DM + h * HD + dq * 4]);
            *reinterpret_cast<uint4*>(&VT[kp * 72 + dq * 4]) = v4;
        }
        bar_g(barid);

        #pragma unroll
        for (int half = 0; half < 2; half++) {
            const int nb = half * 4;

            float s[2][4][4];
            #pragma unroll
            for (int nt = 0; nt < 4; nt++) {
                #pragma unroll
                for (int i = 0; i < 2; i++)
                    #pragma unroll
                    for (int t = 0; t < 4; t++) s[i][nt][t] = 0.f;
                const uint4* kp4 = reinterpret_cast<const uint4*>(
                    &KB[((nb + nt) * 8 + g) * 48 + r * 12]);
                uint4 W0 = kp4[0], W1 = kp4[1];
                unsigned w[8] = {W0.x, W0.y, W0.z, W0.w, W1.x, W1.y, W1.z, W1.w};
                #pragma unroll
                for (int kt = 0; kt < 4; kt++) {
                    mma_f16(s[0][nt], qa[0][kt], w[2 * kt], w[2 * kt + 1]);
                    mma_f16(s[1][nt], qa[1][kt], w[2 * kt], w[2 * kt + 1]);
                }
            }

            #pragma unroll
            for (int i = 0; i < 2; i++)
                #pragma unroll
                for (int nt = 0; nt < 4; nt++) {
                    s[i][nt][0] = fex2(s[i][nt][0]);
                    s[i][nt][1] = fex2(s[i][nt][1]);
                    s[i][nt][2] = fex2(s[i][nt][2]);
                    s[i][nt][3] = fex2(s[i][nt][3]);
                    lsum[i][0] += s[i][nt][0] + s[i][nt][1];
                    lsum[i][1] += s[i][nt][2] + s[i][nt][3];
                }

            unsigned pa[2][2][4];
            #pragma unroll
            for (int i = 0; i < 2; i++)
                #pragma unroll
                for (int kt2 = 0; kt2 < 2; kt2++) {
                    pa[i][kt2][0] = packh2(s[i][2 * kt2][0],     s[i][2 * kt2][1]);
                    pa[i][kt2][1] = packh2(s[i][2 * kt2][2],     s[i][2 * kt2][3]);
                    pa[i][kt2][2] = packh2(s[i][2 * kt2 + 1][0], s[i][2 * kt2 + 1][1]);
                    pa[i][kt2][3] = packh2(s[i][2 * kt2 + 1][2], s[i][2 * kt2 + 1][3]);
                }

            #pragma unroll
            for (int kt2 = 0; kt2 < 2; kt2++) {
                const int kpb = half * 16 + kt2 * 8;
                #pragma unroll
                for (int nt = 0; nt < 8; nt++) {
                    unsigned b0 = VT[(kpb + r)     * 72 + nt * 8 + g];
                    unsigned b1 = VT[(kpb + r + 4) * 72 + nt * 8 + g];
                    mma_f16(o[0][nt], pa[0][kt2], b0, b1);
                    mma_f16(o[1][nt], pa[1][kt2], b0, b1);
                }
            }
        }
        bar_g(barid);
    }

    const int qb = warp * 32;
    #pragma unroll
    for (int i = 0; i < 2; i++) {
        float l0 = lsum[i][0], l1 = lsum[i][1];
        l0 += __shfl_xor_sync(0xffffffffu, l0, 1);
        l0 += __shfl_xor_sync(0xffffffffu, l0, 2);
        l1 += __shfl_xor_sync(0xffffffffu, l1, 1);
        l1 += __shfl_xor_sync(0xffffffffu, l1, 2);
        float inv0 = 1.0f / l0, inv1 = 1.0f / l1;
        #pragma unroll
        for (int nt = 0; nt < 8; nt++) {
            int pcol = h * 32 + nt * 4 + r;
            g_ctxh[(long)(i0 + qb + i * 16 + g) * (DM / 2) + pcol] =
                packh2(o[i][nt][0] * inv0, o[i][nt][1] * inv0);
            g_ctxh[(long)(i0 + qb + i * 16 + g + 8) * (DM / 2) + pcol] =
                packh2(o[i][nt][2] * inv1, o[i][nt][3] * inv1);
        }
    }
}

// --------------------------------------------------------------------------
// Persistent mega-kernel: 148 CTAs x 256 threads, software grid barriers.
// --------------------------------------------------------------------------
__global__ void __launch_bounds__(256, 1) mega(
    const float* __restrict__ X,  const float* __restrict__ Wq,
    const float* __restrict__ Wdkv, const float* __restrict__ Wuk,
    const float* __restrict__ Wuv, const float* __restrict__ Wo,
    const float* __restrict__ wW, const float* __restrict__ wb,
    float* __restrict__ out)
{
    extern __shared__ unsigned smem[];
    const unsigned ph0 = g_phase;
    const int c = blockIdx.x;
    const float QSCALE = 0.125f * 1.4426950408889634f;

    // Phase 0: fp32 -> half conversions (once per run)
    conv_all(X, Wq, Wdkv, Wuk, Wuv, Wo, wW);
    grid_bar(ph0 + 1);

    // Phase A: 32 ckv + 116 q
    if (c < 32) {
        gemm_tile<2>(smem, g_xh, g_wdkvh, nullptr, nullptr, g_ckvh,
                     DM, DM / 2, LAT, LAT, (c >> 1) * 128, (c & 1) * 128, 1.f);
    } else {
        int qi = c - 32;
        gemm_tile<2>(smem, g_xh, g_wqh, nullptr, nullptr, g_qh,
                     DM, DM / 2, DM, DM, (qi >> 3) * 128, (qi & 7) * 128, QSCALE);
    }
    grid_bar(ph0 + 2);

    // Phase B: 128 k + 128 v + 12 leftover q
    for (int t = c; t < 268; t += NCTA) {
        if (t < 128) {
            gemm_tile<2>(smem, g_ckvh, g_wukh, nullptr, nullptr, g_kh,
                         LAT, LAT / 2, DM, DM, (t >> 3) * 128, (t & 7) * 128, 1.f);
        } else if (t < 256) {
            int tt = t - 128;
            gemm_tile<3>(smem, g_ckvh, g_wuvh, nullptr, nullptr, g_vt,
                         LAT, LAT / 2, DM, DM, (tt >> 3) * 128, (tt & 7) * 128, 1.f);
        } else {
            int qi = 116 + (t - 256);
            gemm_tile<2>(smem, g_xh, g_wqh, nullptr, nullptr, g_qh,
                         DM, DM / 2, DM, DM, (qi >> 3) * 128, (qi & 7) * 128, QSCALE);
        }
    }
    grid_bar(ph0 + 3);

    // Phase C: flash — two 4-warp groups per CTA, 256 (head, qtile) tasks
    {
        int group = threadIdx.x >> 7;
        int t = c * 2 + group;
        if (t < 256)
            flash_group(smem + group * 11520, 1 + group, t >> 4, (t & 15) * 128);
    }
    grid_bar(ph0 + 4);

    // Phase D: body -> out[:, 0:1024] fp32 + g_bodyh half
    if (c < 128)
        gemm_tile<4>(smem, g_ctxh, g_woh, nullptr, out, g_bodyh,
                     DM, DM / 2, DM, 2048, (c >> 3) * 128, (c & 7) * 128, 1.f);
    grid_bar(ph0 + 5);

    // Phase E: wheels -> out[:, 1024:2048]
    if (c < 128) {
        int w = c >> 5, tt = c & 31;
        gemm_tile<0>(smem, g_bodyh, g_wwh + (long)w * (DM / 2) * 256,
                     wb + w * 256, out + 1024 + w * 256, nullptr,
                     DM, DM / 2, 256, 2048, (tt >> 1) * 128, (tt & 1) * 128, 1.f);
    }
}

// --------------------------------------------------------------------------
// Launcher: ONE kernel.
// --------------------------------------------------------------------------
extern "C" void kernel_launch(void* const* d_in, const int* in_sizes, int n_in,
                              void* d_out, int out_size)
{
    const float* X    = (const float*)d_in[0];
    const float* Wq   = (const float*)d_in[1];
    const float* Wdkv = (const float*)d_in[2];
    const float* Wuk  = (const float*)d_in[3];
    const float* Wuv  = (const float*)d_in[4];
    const float* Wo   = (const float*)d_in[5];
    const float* wW   = (const float*)d_in[6];
    const float* wb   = (const float*)d_in[7];
    float* out = (float*)d_out;

    const int smem = 23040 * (int)sizeof(unsigned);  // 92160 B
    cudaFuncSetAttribute(mega, cudaFuncAttributeMaxDynamicSharedMemorySize, smem);
    mega<<<NCTA, 256, smem>>>(X, Wq, Wdkv, Wuk, Wuv, Wo, wW, wb, out);
}